// round 15
// baseline (speedup 1.0000x reference)
#include <cuda_runtime.h>
#include <cuda_fp16.h>
#include <math.h>
#include <stdint.h>

// Problem constants
#define Bn    16
#define CINc  8
#define SEQ   32
#define Hh    128
#define Ww    128
#define COUTc 8
#define ZC    32      // 4*COUT gate channels (N)
#define CTOT  16      // CIN + COUT
#define KTOT  144     // 9 taps * 16 channels (K); k = tap*16 + c

#define NT    256     // 8 warps; warp w: output row yl=w>>2, x0=(w&3)*32
#define XPU   136     // strip row pitch in u64 entries; left pad 1
#define NPL   16      // 4 y-rows x 4 interleaved channel-pair planes

// dynamic smem layout (bytes)
// strip entry: uint2 { pack(ch 2cp,2cp+1) , pack(ch 8+2cp,9+2cp) }
#define S_XH   0
#define S_XL   (NPL * XPU * 8)            // 17408
#define S_B    (2 * NPL * XPU * 8)        // 34816
#define S_BIAS (S_B + 9 * 4 * 32 * 16)    // +18432 = 53248
#define S_TOTAL (S_BIAS + 128)            // 53376

#define STATE_ELEMS (Bn * COUTc * Hh * Ww)
__device__ float g_h[2][STATE_ELEMS];   // ping-pong h (cross-block halo safety)
__device__ float g_c[STATE_ELEMS];
// B operands: [tap][nt][lane] -> uint4 {bh0, bh1, bl0, bl1}
__device__ __align__(16) uint4 g_B2[9 * 4 * 32];

__device__ __forceinline__ float sigf(float x) {
    return __fdividef(1.0f, 1.0f + __expf(-x));
}
__device__ __forceinline__ float tanhfast(float x) {
    return __fdividef(2.0f, 1.0f + __expf(-2.0f * x)) - 1.0f;
}

// pack two f32 into f16x2 (lo half = v0) and the f16x2 residual pack
__device__ __forceinline__ void pack_split(float v0, float v1,
                                           uint32_t& hi, uint32_t& lo) {
    asm("cvt.rn.f16x2.f32 %0, %1, %2;" : "=r"(hi) : "f"(v1), "f"(v0));
    float h0, h1;
    asm("{ .reg .b16 l,h; mov.b32 {l,h}, %2; cvt.f32.f16 %0, l; cvt.f32.f16 %1, h; }"
        : "=f"(h0), "=f"(h1) : "r"(hi));
    float r0 = v0 - h0, r1 = v1 - h1;
    asm("cvt.rn.f16x2.f32 %0, %1, %2;" : "=r"(lo) : "f"(r1), "f"(r0));
}

__device__ __forceinline__ void mma16816(float* d, const uint32_t* a,
                                         uint32_t b0, uint32_t b1) {
    asm volatile(
        "mma.sync.aligned.m16n8k16.row.col.f32.f16.f16.f32 "
        "{%0,%1,%2,%3}, {%4,%5,%6,%7}, {%8,%9}, {%0,%1,%2,%3};"
        : "+f"(d[0]), "+f"(d[1]), "+f"(d[2]), "+f"(d[3])
        : "r"(a[0]), "r"(a[1]), "r"(a[2]), "r"(a[3]), "r"(b0), "r"(b1));
}

// ---- prep: B fragment quads per (tap, nt, lane); n = nt*8+g, c0 = tg*2
// B[n][k] = Wc[n*144 + c*9 + tap], k = tap*16 + c
__global__ void prep_B(const float* __restrict__ Wc) {
    for (int i = threadIdx.x; i < 9 * 4 * 32; i += blockDim.x) {
        int lane = i & 31;
        int nt   = (i >> 5) & 3;
        int tap  = i / 128;
        int g2   = lane >> 2;
        int tg   = lane & 3;
        int n    = nt * 8 + g2;
        int c0   = tg * 2;
        float w00 = Wc[n * KTOT + (c0    ) * 9 + tap];
        float w01 = Wc[n * KTOT + (c0 + 1) * 9 + tap];
        float w10 = Wc[n * KTOT + (c0 + 8) * 9 + tap];
        float w11 = Wc[n * KTOT + (c0 + 9) * 9 + tap];
        uint32_t h0, l0, h1, l1;
        pack_split(w00, w01, h0, l0);
        pack_split(w10, w11, h1, l1);
        g_B2[i] = make_uint4(h0, h1, l0, l1);
    }
}

// ---- main: one CTA = TWO image rows (M=256 px) x N=32 x K=144 ----
template <bool FIRST>
__global__ __launch_bounds__(NT, 4)
void convlstm_hmma(const float* __restrict__ X,
                   const float* __restrict__ bc,
                   float* __restrict__ out,
                   int t)
{
    extern __shared__ __align__(16) char smem[];
    uint2* s_xh   = reinterpret_cast<uint2*>(smem + S_XH);
    uint2* s_xl   = reinterpret_cast<uint2*>(smem + S_XL);
    uint4* s_b2   = reinterpret_cast<uint4*>(smem + S_B);
    float* s_bias = reinterpret_cast<float*>(smem + S_BIAS);

    const int tid  = threadIdx.x;
    const int w    = tid >> 5;
    const int lane = tid & 31;
    const int g    = lane >> 2;   // fragment row within tile
    const int tg   = lane & 3;    // fragment k-col pair (= interleaved plane)
    const int yl   = w >> 2;      // 0/1: which output row of the pair
    const int x0   = (w & 3) * 32;
    const int y0 = blockIdx.x * 2, b = blockIdx.y;

    const float* __restrict__ h_prev = g_h[(t + 1) & 1];
    float* __restrict__ h_cur = g_h[t & 1];

    // zero only the pad columns actually read: col 0 and col 129, both splits
    if (tid < NPL * 4) {
        int pl  = tid >> 2;
        int r   = tid & 3;
        int col = (r & 1) ? 129 : 0;
        uint2* s = (r >> 1) ? s_xl : s_xh;
        s[pl * XPU + col] = make_uint2(0u, 0u);
    }
    // copy B quads
    {
        const uint4* sb = g_B2;
        for (int i = tid; i < 9 * 4 * 32; i += NT) s_b2[i] = sb[i];
    }
    if (tid < ZC) s_bias[tid] = bc[tid];

    // fill strip: interleaved plane pl = r*4 + cp (cp = 0..3).
    // entry.x = pack(X ch 2cp, 2cp+1); entry.y = pack(h ch 2cp, 2cp+1).
    // input x = xi -> strip col xi+1.
    for (int i = tid; i < NPL * 32; i += NT) {
        int pl = i >> 5;
        int x4 = (i & 31) * 4;    // xi base (0..124, step 4)
        int r  = pl >> 2;
        int cp = pl & 3;
        int gy = y0 + r - 1;
        float4 xa = make_float4(0.f, 0.f, 0.f, 0.f), xb = xa;
        float4 ha = xa, hb = xa;
        if (gy >= 0 && gy < Hh) {
            size_t xbase = (((size_t)(b * CINc + 2 * cp) * SEQ + t) * Hh + gy) * Ww + x4;
            xa = *reinterpret_cast<const float4*>(X + xbase);
            xb = *reinterpret_cast<const float4*>(X + xbase + (size_t)SEQ * Hh * Ww);
            if (!FIRST) {
                size_t hbase = ((size_t)(b * COUTc + 2 * cp) * Hh + gy) * Ww + x4;
                ha = *reinterpret_cast<const float4*>(h_prev + hbase);
                hb = *reinterpret_cast<const float4*>(h_prev + hbase + (size_t)Hh * Ww);
            }
        }
        const int o = pl * XPU + x4 + 1;
        uint32_t xh_, xl_, hh_, hl_;
        pack_split(xa.x, xb.x, xh_, xl_); pack_split(ha.x, hb.x, hh_, hl_);
        s_xh[o]     = make_uint2(xh_, hh_); s_xl[o]     = make_uint2(xl_, hl_);
        pack_split(xa.y, xb.y, xh_, xl_); pack_split(ha.y, hb.y, hh_, hl_);
        s_xh[o + 1] = make_uint2(xh_, hh_); s_xl[o + 1] = make_uint2(xl_, hl_);
        pack_split(xa.z, xb.z, xh_, xl_); pack_split(ha.z, hb.z, hh_, hl_);
        s_xh[o + 2] = make_uint2(xh_, hh_); s_xl[o + 2] = make_uint2(xl_, hl_);
        pack_split(xa.w, xb.w, xh_, xl_); pack_split(ha.w, hb.w, hh_, hl_);
        s_xh[o + 3] = make_uint2(xh_, hh_); s_xl[o + 3] = make_uint2(xl_, hl_);
    }
    __syncthreads();

    // accumulators: [m-tile][n-tile][frag reg]
    float d[2][4][4];
#pragma unroll
    for (int mt = 0; mt < 2; mt++)
#pragma unroll
        for (int nt = 0; nt < 4; nt++)
#pragma unroll
            for (int r = 0; r < 4; r++) d[mt][nt][r] = 0.0f;

#pragma unroll
    for (int tap = 0; tap < 9; tap++) {
        const int ky = tap / 3;
        const int kx = tap - ky * 3;
        // A base: interleaved plane (yl+ky)*4 + tg; col = x0 + g + kx.
        const int xoff = ((yl + ky) * 4 + tg) * XPU + (x0 + g + kx);

        uint32_t ah[2][4], al[2][4];
#pragma unroll
        for (int mt = 0; mt < 2; mt++) {
            const int o = xoff + mt * 16;
            uint2 h0 = s_xh[o];       // {row g  klo, row g  khi}
            uint2 h1 = s_xh[o + 8];   // {row g+8 klo, row g+8 khi}
            uint2 l0 = s_xl[o];
            uint2 l1 = s_xl[o + 8];
            ah[mt][0] = h0.x; ah[mt][1] = h1.x; ah[mt][2] = h0.y; ah[mt][3] = h1.y;
            al[mt][0] = l0.x; al[mt][1] = l1.x; al[mt][2] = l0.y; al[mt][3] = l1.y;
        }

#pragma unroll
        for (int nt = 0; nt < 4; nt++) {
            const int bi = (tap * 4 + nt) * 32 + lane;
            uint4 bq = s_b2[bi];
#pragma unroll
            for (int mt = 0; mt < 2; mt++) {
                mma16816(d[mt][nt], ah[mt], bq.x, bq.y);  // Ah*Bh
                mma16816(d[mt][nt], al[mt], bq.x, bq.y);  // Al*Bh
                mma16816(d[mt][nt], ah[mt], bq.z, bq.w);  // Ah*Bl
            }
        }
    }

    // ---- epilogue: gates + state + output ----
    const int y = y0 + yl;
#pragma unroll
    for (int mt = 0; mt < 2; mt++) {
#pragma unroll
        for (int rs = 0; rs < 2; rs++) {
            const int x = x0 + mt * 16 + rs * 8 + g;
#pragma unroll
            for (int e = 0; e < 2; e++) {
                const int ch = tg * 2 + e;
                const int ri = rs * 2 + e;
                float zi = d[mt][0][ri] + s_bias[ch];
                float zf = d[mt][1][ri] + s_bias[8 + ch];
                float zg = d[mt][2][ri] + s_bias[16 + ch];
                float zo = d[mt][3][ri] + s_bias[24 + ch];

                float ig = sigf(zi);
                float fg = sigf(zf);
                float gg = tanhfast(zg);
                float og = sigf(zo);

                size_t sidx = ((size_t)(b * COUTc + ch) * Hh + y) * Ww + x;
                float cp = FIRST ? 0.0f : g_c[sidx];
                float cn = fg * cp + ig * gg;
                float hn = og * tanhfast(cn);
                g_c[sidx] = cn;
                h_cur[sidx] = hn;
                out[((size_t)(b * COUTc + ch) * SEQ + t) * (Hh * Ww)
                    + (size_t)y * Ww + x] = hn;
            }
        }
    }
}

extern "C" void kernel_launch(void* const* d_in, const int* in_sizes, int n_in,
                              void* d_out, int out_size)
{
    const float* X  = (const float*)d_in[0];
    const float* Wc = (const float*)d_in[1];
    const float* bc = (const float*)d_in[2];
    float* out = (float*)d_out;

    cudaFuncSetAttribute(convlstm_hmma<true>,
                         cudaFuncAttributeMaxDynamicSharedMemorySize, S_TOTAL);
    cudaFuncSetAttribute(convlstm_hmma<false>,
                         cudaFuncAttributeMaxDynamicSharedMemorySize, S_TOTAL);

    prep_B<<<1, 256>>>(Wc);

    dim3 grid(Hh / 2, Bn);   // (row-pair, batch): 1024 CTAs x 256 threads
    convlstm_hmma<true><<<grid, NT, S_TOTAL>>>(X, bc, out, 0);
    for (int t = 1; t < SEQ; t++) {
        convlstm_hmma<false><<<grid, NT, S_TOTAL>>>(X, bc, out, t);
    }
}

// round 16
// speedup vs baseline: 1.7325x; 1.7325x over previous
#include <cuda_runtime.h>
#include <cuda_fp16.h>
#include <math.h>
#include <stdint.h>

// Problem constants
#define Bn    16
#define CINc  8
#define SEQ   32
#define Hh    128
#define Ww    128
#define COUTc 8
#define ZC    32      // 4*COUT gate channels (N)
#define CTOT  16      // CIN + COUT
#define KTOT  144     // 9 taps * 16 channels (K); k = tap*16 + c

#define NT    256     // 8 warps; warp w: output row yl=w>>2, x0=(w&3)*32
#define XPU   136     // strip row pitch in u32 (f16x2); left pad 1, conflict-free
#define NPP   32      // 4 y-rows x 8 channel-pairs

// dynamic smem layout (bytes). A strip is f16 only (no lo split):
// weights stay exact via B hi+lo; inputs rounded to f16 (incoherent error).
#define S_XH   0
#define S_B    (NPP * XPU * 4)            // 17408
#define S_BIAS (S_B + 9 * 4 * 32 * 16)    // +18432 = 35840
#define S_TOTAL (S_BIAS + 128)            // 35968

#define STATE_ELEMS (Bn * COUTc * Hh * Ww)
__device__ float g_h[2][STATE_ELEMS];   // ping-pong h (cross-block halo safety)
__device__ float g_c[STATE_ELEMS];
// B operands: [tap][nt][lane] -> uint4 {bh0, bh1, bl0, bl1}
__device__ __align__(16) uint4 g_B2[9 * 4 * 32];

__device__ __forceinline__ float sigf(float x) {
    return __fdividef(1.0f, 1.0f + __expf(-x));
}
__device__ __forceinline__ float tanhfast(float x) {
    return __fdividef(2.0f, 1.0f + __expf(-2.0f * x)) - 1.0f;
}

// pack two f32 into f16x2 (lo half = v0)
__device__ __forceinline__ uint32_t pack2f16(float v0, float v1) {
    uint32_t r;
    asm("cvt.rn.f16x2.f32 %0, %1, %2;" : "=r"(r) : "f"(v1), "f"(v0));
    return r;
}
// pack + residual pack (used only in weight prep)
__device__ __forceinline__ void pack_split(float v0, float v1,
                                           uint32_t& hi, uint32_t& lo) {
    asm("cvt.rn.f16x2.f32 %0, %1, %2;" : "=r"(hi) : "f"(v1), "f"(v0));
    float h0, h1;
    asm("{ .reg .b16 l,h; mov.b32 {l,h}, %2; cvt.f32.f16 %0, l; cvt.f32.f16 %1, h; }"
        : "=f"(h0), "=f"(h1) : "r"(hi));
    float r0 = v0 - h0, r1 = v1 - h1;
    asm("cvt.rn.f16x2.f32 %0, %1, %2;" : "=r"(lo) : "f"(r1), "f"(r0));
}

__device__ __forceinline__ void mma16816(float* d, const uint32_t* a,
                                         uint32_t b0, uint32_t b1) {
    asm volatile(
        "mma.sync.aligned.m16n8k16.row.col.f32.f16.f16.f32 "
        "{%0,%1,%2,%3}, {%4,%5,%6,%7}, {%8,%9}, {%0,%1,%2,%3};"
        : "+f"(d[0]), "+f"(d[1]), "+f"(d[2]), "+f"(d[3])
        : "r"(a[0]), "r"(a[1]), "r"(a[2]), "r"(a[3]), "r"(b0), "r"(b1));
}

// ---- prep: B fragment quads per (tap, nt, lane); n = nt*8+g, c0 = tg*2
// B[n][k] = Wc[n*144 + c*9 + tap], k = tap*16 + c
__global__ void prep_B(const float* __restrict__ Wc) {
    for (int i = threadIdx.x; i < 9 * 4 * 32; i += blockDim.x) {
        int lane = i & 31;
        int nt   = (i >> 5) & 3;
        int tap  = i / 128;
        int g2   = lane >> 2;
        int tg   = lane & 3;
        int n    = nt * 8 + g2;
        int c0   = tg * 2;
        float w00 = Wc[n * KTOT + (c0    ) * 9 + tap];
        float w01 = Wc[n * KTOT + (c0 + 1) * 9 + tap];
        float w10 = Wc[n * KTOT + (c0 + 8) * 9 + tap];
        float w11 = Wc[n * KTOT + (c0 + 9) * 9 + tap];
        uint32_t h0, l0, h1, l1;
        pack_split(w00, w01, h0, l0);
        pack_split(w10, w11, h1, l1);
        g_B2[i] = make_uint4(h0, h1, l0, l1);
    }
}

// ---- main: one CTA = TWO image rows (M=256 px) x N=32 x K=144 ----
template <bool FIRST>
__global__ __launch_bounds__(NT, 4)
void convlstm_hmma(const float* __restrict__ X,
                   const float* __restrict__ bc,
                   float* __restrict__ out,
                   int t)
{
    extern __shared__ __align__(16) char smem[];
    uint32_t* s_xh  = reinterpret_cast<uint32_t*>(smem + S_XH);
    uint4*    s_b2  = reinterpret_cast<uint4*>(smem + S_B);
    float*    s_bias = reinterpret_cast<float*>(smem + S_BIAS);

    const int tid  = threadIdx.x;
    const int w    = tid >> 5;
    const int lane = tid & 31;
    const int g    = lane >> 2;   // fragment row within tile
    const int tg   = lane & 3;    // fragment k-col pair
    const int yl   = w >> 2;      // 0/1: which output row of the pair
    const int x0   = (w & 3) * 32;
    const int y0 = blockIdx.x * 2, b = blockIdx.y;

    const float* __restrict__ h_prev = g_h[(t + 1) & 1];
    float* __restrict__ h_cur = g_h[t & 1];

    // zero only the pad columns actually read: col 0 and col 129
    if (tid < NPP * 2) {
        int p   = tid >> 1;
        int col = (tid & 1) ? 129 : 0;
        s_xh[p * XPU + col] = 0u;
    }
    // copy B quads
    for (int i = tid; i < 9 * 4 * 32; i += NT) s_b2[i] = g_B2[i];
    if (tid < ZC) s_bias[tid] = bc[tid];

    // fill strip (vectorized float4): pair-plane p = r*8 + cp; always stores
    // (zeros when out of range / FIRST h). input x = xi -> strip col xi+1.
    for (int i = tid; i < NPP * 32; i += NT) {
        int p  = i >> 5;
        int x4 = (i & 31) * 4;    // xi base (0..124, step 4)
        int r  = p >> 3;
        int cp = p & 7;
        int gy = y0 + r - 1;
        int c  = cp * 2;
        float4 a0 = make_float4(0.f, 0.f, 0.f, 0.f);
        float4 a1 = a0;
        if (gy >= 0 && gy < Hh) {
            if (c < CINc) {
                size_t base = (((size_t)(b * CINc + c) * SEQ + t) * Hh + gy) * Ww + x4;
                a0 = *reinterpret_cast<const float4*>(X + base);
                a1 = *reinterpret_cast<const float4*>(X + base + (size_t)SEQ * Hh * Ww);
            } else if (!FIRST) {
                size_t base = ((size_t)(b * COUTc + (c - CINc)) * Hh + gy) * Ww + x4;
                a0 = *reinterpret_cast<const float4*>(h_prev + base);
                a1 = *reinterpret_cast<const float4*>(h_prev + base + (size_t)Hh * Ww);
            }
        }
        const int o = p * XPU + x4 + 1;
        s_xh[o]     = pack2f16(a0.x, a1.x);
        s_xh[o + 1] = pack2f16(a0.y, a1.y);
        s_xh[o + 2] = pack2f16(a0.z, a1.z);
        s_xh[o + 3] = pack2f16(a0.w, a1.w);
    }
    __syncthreads();

    // accumulators: [m-tile][n-tile][frag reg]
    float d[2][4][4];
#pragma unroll
    for (int mt = 0; mt < 2; mt++)
#pragma unroll
        for (int nt = 0; nt < 4; nt++)
#pragma unroll
            for (int r = 0; r < 4; r++) d[mt][nt][r] = 0.0f;

#pragma unroll
    for (int tap = 0; tap < 9; tap++) {
        const int ky = tap / 3;
        const int kx = tap - ky * 3;
        // A base: pair-plane (yl+ky)*8 + tg; col = x0 + g + kx (pad absorbed).
        const int xoff = ((yl + ky) * 8 + tg) * XPU + (x0 + g + kx);
        const uint32_t* xh = s_xh + xoff;

        uint32_t ah[2][4];
#pragma unroll
        for (int mt = 0; mt < 2; mt++) {
            const int m16 = mt * 16;
            ah[mt][0] = xh[m16];
            ah[mt][1] = xh[m16 + 8];
            ah[mt][2] = xh[4 * XPU + m16];
            ah[mt][3] = xh[4 * XPU + m16 + 8];
        }

#pragma unroll
        for (int nt = 0; nt < 4; nt++) {
            const int bi = (tap * 4 + nt) * 32 + lane;
            uint4 bq = s_b2[bi];
#pragma unroll
            for (int mt = 0; mt < 2; mt++) {
                mma16816(d[mt][nt], ah[mt], bq.x, bq.y);  // Ah*Bh
                mma16816(d[mt][nt], ah[mt], bq.z, bq.w);  // Ah*Bl (weights exact)
            }
        }
    }

    // ---- epilogue: gates + state + output ----
    const int y = y0 + yl;
#pragma unroll
    for (int mt = 0; mt < 2; mt++) {
#pragma unroll
        for (int rs = 0; rs < 2; rs++) {
            const int x = x0 + mt * 16 + rs * 8 + g;
#pragma unroll
            for (int e = 0; e < 2; e++) {
                const int ch = tg * 2 + e;
                const int ri = rs * 2 + e;
                float zi = d[mt][0][ri] + s_bias[ch];
                float zf = d[mt][1][ri] + s_bias[8 + ch];
                float zg = d[mt][2][ri] + s_bias[16 + ch];
                float zo = d[mt][3][ri] + s_bias[24 + ch];

                float ig = sigf(zi);
                float fg = sigf(zf);
                float gg = tanhfast(zg);
                float og = sigf(zo);

                size_t sidx = ((size_t)(b * COUTc + ch) * Hh + y) * Ww + x;
                float cp = FIRST ? 0.0f : g_c[sidx];
                float cn = fg * cp + ig * gg;
                float hn = og * tanhfast(cn);
                g_c[sidx] = cn;
                h_cur[sidx] = hn;
                out[((size_t)(b * COUTc + ch) * SEQ + t) * (Hh * Ww)
                    + (size_t)y * Ww + x] = hn;
            }
        }
    }
}

extern "C" void kernel_launch(void* const* d_in, const int* in_sizes, int n_in,
                              void* d_out, int out_size)
{
    const float* X  = (const float*)d_in[0];
    const float* Wc = (const float*)d_in[1];
    const float* bc = (const float*)d_in[2];
    float* out = (float*)d_out;

    cudaFuncSetAttribute(convlstm_hmma<true>,
                         cudaFuncAttributeMaxDynamicSharedMemorySize, S_TOTAL);
    cudaFuncSetAttribute(convlstm_hmma<false>,
                         cudaFuncAttributeMaxDynamicSharedMemorySize, S_TOTAL);

    prep_B<<<1, 256>>>(Wc);

    dim3 grid(Hh / 2, Bn);   // (row-pair, batch): 1024 CTAs x 256 threads
    convlstm_hmma<true><<<grid, NT, S_TOTAL>>>(X, bc, out, 0);
    for (int t = 1; t < SEQ; t++) {
        convlstm_hmma<false><<<grid, NT, S_TOTAL>>>(X, bc, out, t);
    }
}

// round 17
// speedup vs baseline: 1.7811x; 1.0280x over previous
#include <cuda_runtime.h>
#include <cuda_fp16.h>
#include <math.h>
#include <stdint.h>

// Problem constants
#define Bn    16
#define CINc  8
#define SEQ   32
#define Hh    128
#define Ww    128
#define COUTc 8
#define ZC    32      // 4*COUT gate channels (N)
#define CTOT  16      // CIN + COUT
#define KTOT  144     // 9 taps * 16 channels (K); k = tap*16 + c
#define HW    (Hh * Ww)

#define NT    256     // 8 warps; warp w: output row yl=w>>2, x0=(w&3)*32
#define XPU   136     // strip row pitch in u32 (f16x2); left pad 1, conflict-free
#define NPP   32      // 4 y-rows x 8 channel-pairs

// dynamic smem layout (bytes). A strip is f16 only (no lo split):
// weights stay exact via B hi+lo; inputs rounded to f16 (incoherent error).
#define S_XH   0
#define S_B    (NPP * XPU * 4)            // 17408
#define S_BIAS (S_B + 9 * 4 * 32 * 16)    // +18432 = 35840
#define S_TOTAL (S_BIAS + 128)            // 35968

#define STATE_ELEMS (Bn * COUTc * Hh * Ww)
// h state lives inside `out` (h_t == out[:, :, t]); only c needs scratch.
__device__ float g_c[STATE_ELEMS];
// B operands: [tap][nt][lane] -> uint4 {bh0, bh1, bl0, bl1}
__device__ __align__(16) uint4 g_B2[9 * 4 * 32];

__device__ __forceinline__ float sigf(float x) {
    return __fdividef(1.0f, 1.0f + __expf(-x));
}
__device__ __forceinline__ float tanhfast(float x) {
    return __fdividef(2.0f, 1.0f + __expf(-2.0f * x)) - 1.0f;
}

// pack two f32 into f16x2 (lo half = v0)
__device__ __forceinline__ uint32_t pack2f16(float v0, float v1) {
    uint32_t r;
    asm("cvt.rn.f16x2.f32 %0, %1, %2;" : "=r"(r) : "f"(v1), "f"(v0));
    return r;
}
// pack + residual pack (used only in weight prep)
__device__ __forceinline__ void pack_split(float v0, float v1,
                                           uint32_t& hi, uint32_t& lo) {
    asm("cvt.rn.f16x2.f32 %0, %1, %2;" : "=r"(hi) : "f"(v1), "f"(v0));
    float h0, h1;
    asm("{ .reg .b16 l,h; mov.b32 {l,h}, %2; cvt.f32.f16 %0, l; cvt.f32.f16 %1, h; }"
        : "=f"(h0), "=f"(h1) : "r"(hi));
    float r0 = v0 - h0, r1 = v1 - h1;
    asm("cvt.rn.f16x2.f32 %0, %1, %2;" : "=r"(lo) : "f"(r1), "f"(r0));
}

__device__ __forceinline__ void mma16816(float* d, const uint32_t* a,
                                         uint32_t b0, uint32_t b1) {
    asm volatile(
        "mma.sync.aligned.m16n8k16.row.col.f32.f16.f16.f32 "
        "{%0,%1,%2,%3}, {%4,%5,%6,%7}, {%8,%9}, {%0,%1,%2,%3};"
        : "+f"(d[0]), "+f"(d[1]), "+f"(d[2]), "+f"(d[3])
        : "r"(a[0]), "r"(a[1]), "r"(a[2]), "r"(a[3]), "r"(b0), "r"(b1));
}

// ---- prep: B fragment quads per (tap, nt, lane); n = nt*8+g, c0 = tg*2
// B[n][k] = Wc[n*144 + c*9 + tap], k = tap*16 + c
__global__ void prep_B(const float* __restrict__ Wc) {
    for (int i = threadIdx.x; i < 9 * 4 * 32; i += blockDim.x) {
        int lane = i & 31;
        int nt   = (i >> 5) & 3;
        int tap  = i / 128;
        int g2   = lane >> 2;
        int tg   = lane & 3;
        int n    = nt * 8 + g2;
        int c0   = tg * 2;
        float w00 = Wc[n * KTOT + (c0    ) * 9 + tap];
        float w01 = Wc[n * KTOT + (c0 + 1) * 9 + tap];
        float w10 = Wc[n * KTOT + (c0 + 8) * 9 + tap];
        float w11 = Wc[n * KTOT + (c0 + 9) * 9 + tap];
        uint32_t h0, l0, h1, l1;
        pack_split(w00, w01, h0, l0);
        pack_split(w10, w11, h1, l1);
        g_B2[i] = make_uint4(h0, h1, l0, l1);
    }
}

// ---- main: one CTA = TWO image rows (M=256 px) x N=32 x K=144 ----
template <bool FIRST>
__global__ __launch_bounds__(NT, 4)
void convlstm_hmma(const float* __restrict__ X,
                   const float* __restrict__ bc,
                   float* __restrict__ out,
                   int t)
{
    extern __shared__ __align__(16) char smem[];
    uint32_t* s_xh  = reinterpret_cast<uint32_t*>(smem + S_XH);
    uint4*    s_b2  = reinterpret_cast<uint4*>(smem + S_B);
    float*    s_bias = reinterpret_cast<float*>(smem + S_BIAS);

    const int tid  = threadIdx.x;
    const int w    = tid >> 5;
    const int lane = tid & 31;
    const int g    = lane >> 2;   // fragment row within tile
    const int tg   = lane & 3;    // fragment k-col pair
    const int yl   = w >> 2;      // 0/1: which output row of the pair
    const int x0   = (w & 3) * 32;
    const int y0 = blockIdx.x * 2, b = blockIdx.y;

    // zero only the pad columns actually read: col 0 and col 129
    if (tid < NPP * 2) {
        int p   = tid >> 1;
        int col = (tid & 1) ? 129 : 0;
        s_xh[p * XPU + col] = 0u;
    }
    // copy B quads
    for (int i = tid; i < 9 * 4 * 32; i += NT) s_b2[i] = g_B2[i];
    if (tid < ZC) s_bias[tid] = bc[tid];

    // fill strip (vectorized float4): pair-plane p = r*8 + cp; always stores
    // (zeros when out of range / FIRST h). input x = xi -> strip col xi+1.
    // h_{t-1} channels are read from out[:, :, t-1] (h aliased into out).
    for (int i = tid; i < NPP * 32; i += NT) {
        int p  = i >> 5;
        int x4 = (i & 31) * 4;    // xi base (0..124, step 4)
        int r  = p >> 3;
        int cp = p & 7;
        int gy = y0 + r - 1;
        int c  = cp * 2;
        float4 a0 = make_float4(0.f, 0.f, 0.f, 0.f);
        float4 a1 = a0;
        if (gy >= 0 && gy < Hh) {
            if (c < CINc) {
                size_t base = (((size_t)(b * CINc + c) * SEQ + t) * Hh + gy) * Ww + x4;
                a0 = *reinterpret_cast<const float4*>(X + base);
                a1 = *reinterpret_cast<const float4*>(X + base + (size_t)SEQ * HW);
            } else if (!FIRST) {
                size_t base = (((size_t)(b * COUTc + (c - CINc)) * SEQ + (t - 1)) * Hh
                               + gy) * Ww + x4;
                a0 = *reinterpret_cast<const float4*>(out + base);
                a1 = *reinterpret_cast<const float4*>(out + base + (size_t)SEQ * HW);
            }
        }
        const int o = p * XPU + x4 + 1;
        s_xh[o]     = pack2f16(a0.x, a1.x);
        s_xh[o + 1] = pack2f16(a0.y, a1.y);
        s_xh[o + 2] = pack2f16(a0.z, a1.z);
        s_xh[o + 3] = pack2f16(a0.w, a1.w);
    }
    __syncthreads();

    // accumulators: [m-tile][n-tile][frag reg]
    float d[2][4][4];
#pragma unroll
    for (int mt = 0; mt < 2; mt++)
#pragma unroll
        for (int nt = 0; nt < 4; nt++)
#pragma unroll
            for (int r = 0; r < 4; r++) d[mt][nt][r] = 0.0f;

#pragma unroll
    for (int tap = 0; tap < 9; tap++) {
        const int ky = tap / 3;
        const int kx = tap - ky * 3;
        // A base: pair-plane (yl+ky)*8 + tg; col = x0 + g + kx (pad absorbed).
        const int xoff = ((yl + ky) * 8 + tg) * XPU + (x0 + g + kx);
        const uint32_t* xh = s_xh + xoff;

        uint32_t ah[2][4];
#pragma unroll
        for (int mt = 0; mt < 2; mt++) {
            const int m16 = mt * 16;
            ah[mt][0] = xh[m16];
            ah[mt][1] = xh[m16 + 8];
            ah[mt][2] = xh[4 * XPU + m16];
            ah[mt][3] = xh[4 * XPU + m16 + 8];
        }

#pragma unroll
        for (int nt = 0; nt < 4; nt++) {
            const int bi = (tap * 4 + nt) * 32 + lane;
            uint4 bq = s_b2[bi];
#pragma unroll
            for (int mt = 0; mt < 2; mt++) {
                mma16816(d[mt][nt], ah[mt], bq.x, bq.y);  // Ah*Bh
                mma16816(d[mt][nt], ah[mt], bq.z, bq.w);  // Ah*Bl (weights exact)
            }
        }
    }

    // ---- epilogue: gates + state + output (h written only to out) ----
    const int y = y0 + yl;
#pragma unroll
    for (int mt = 0; mt < 2; mt++) {
#pragma unroll
        for (int rs = 0; rs < 2; rs++) {
            const int x = x0 + mt * 16 + rs * 8 + g;
#pragma unroll
            for (int e = 0; e < 2; e++) {
                const int ch = tg * 2 + e;
                const int ri = rs * 2 + e;
                float zi = d[mt][0][ri] + s_bias[ch];
                float zf = d[mt][1][ri] + s_bias[8 + ch];
                float zg = d[mt][2][ri] + s_bias[16 + ch];
                float zo = d[mt][3][ri] + s_bias[24 + ch];

                float ig = sigf(zi);
                float fg = sigf(zf);
                float gg = tanhfast(zg);
                float og = sigf(zo);

                size_t sidx = ((size_t)(b * COUTc + ch) * Hh + y) * Ww + x;
                float cp = FIRST ? 0.0f : g_c[sidx];
                float cn = fg * cp + ig * gg;
                float hn = og * tanhfast(cn);
                g_c[sidx] = cn;
                out[((size_t)(b * COUTc + ch) * SEQ + t) * HW
                    + (size_t)y * Ww + x] = hn;
            }
        }
    }
}

extern "C" void kernel_launch(void* const* d_in, const int* in_sizes, int n_in,
                              void* d_out, int out_size)
{
    const float* X  = (const float*)d_in[0];
    const float* Wc = (const float*)d_in[1];
    const float* bc = (const float*)d_in[2];
    float* out = (float*)d_out;

    cudaFuncSetAttribute(convlstm_hmma<true>,
                         cudaFuncAttributeMaxDynamicSharedMemorySize, S_TOTAL);
    cudaFuncSetAttribute(convlstm_hmma<false>,
                         cudaFuncAttributeMaxDynamicSharedMemorySize, S_TOTAL);

    prep_B<<<1, 256>>>(Wc);

    dim3 grid(Hh / 2, Bn);   // (row-pair, batch): 1024 CTAs x 256 threads
    convlstm_hmma<true><<<grid, NT, S_TOTAL>>>(X, bc, out, 0);
    for (int t = 1; t < SEQ; t++) {
        convlstm_hmma<false><<<grid, NT, S_TOTAL>>>(X, bc, out, t);
    }
}